// round 3
// baseline (speedup 1.0000x reference)
#include <cuda_runtime.h>
#include <math.h>

#define D        128
#define K_NEG    4
#define T        8          // same-relation triples per score block
#define NVEC     (5 * T)    // u-vectors per block (pos + 4 negs per triple)
#define MAX_M    16384
#define MAX_REL  256
#define NPAD_MAX (MAX_M + MAX_REL * T)

// ---- allocation-free scratch (__device__ globals) ----
__device__ float g_loss[MAX_M];
__device__ int   g_cnt[MAX_REL];
__device__ int   g_pos[MAX_REL];
__device__ int   g_off[MAX_REL];
__device__ int   g_order[NPAD_MAX];

// K0: reset counters and poison the padded order array (runs every replay).
__global__ void kg_init_kernel(int npad)
{
    const int i = blockIdx.x * blockDim.x + threadIdx.x;
    if (i < npad) g_order[i] = -1;
    if (i < MAX_REL) { g_cnt[i] = 0; g_pos[i] = 0; }
}

// K1: histogram triples by relation.
__global__ void kg_count_kernel(const int* __restrict__ rel_ids, int M)
{
    const int m = blockIdx.x * blockDim.x + threadIdx.x;
    if (m < M) atomicAdd(&g_cnt[rel_ids[m]], 1);
}

// K2: exclusive prefix over buckets padded to multiples of T (64 entries: 1 thread).
__global__ void kg_offset_kernel(int n_rel)
{
    if (threadIdx.x == 0) {
        int acc = 0;
        for (int r = 0; r < n_rel; r++) {
            g_off[r] = acc;
            acc += ((g_cnt[r] + T - 1) / T) * T;
        }
    }
}

// K3: scatter triple indices into their relation bucket.
__global__ void kg_scatter_kernel(const int* __restrict__ rel_ids, int M)
{
    const int m = blockIdx.x * blockDim.x + threadIdx.x;
    if (m < M) {
        const int r = rel_ids[m];
        const int p = atomicAdd(&g_pos[r], 1);
        g_order[g_off[r] + p] = m;
    }
}

// K4: score. One block per T-slot tile of the grouped order array; all valid
// slots in a block share one relation, so R is loaded once per thread-row and
// amortized over 5*T dot products.
// score_j = || R*(h - t_j) + e ||^2 ; loss per triple from pos vs mean(neg).
__global__ void __launch_bounds__(128) kg_score_kernel(
    const float* __restrict__ mol_emb,        // [B, D]
    const float* __restrict__ entity_emb,     // [N_ENT, D]
    const float* __restrict__ relation_emb,   // [N_REL, D]
    const float* __restrict__ relation_matrix,// [N_REL, D, D]
    const int*   __restrict__ tail_ids,       // [M]
    const int*   __restrict__ rel_ids,        // [M]
    const int*   __restrict__ neg_indices,    // [M, K]
    int n_per_b)
{
    __shared__ float u[NVEC][D];     // 20 KB
    __shared__ float evec[D];
    __shared__ float red[4][NVEC];
    __shared__ int   sm_m[T];
    __shared__ int   sm_rel;

    const int tid = threadIdx.x;
    const int blk = blockIdx.x;

    if (tid < T) sm_m[tid] = g_order[blk * T + tid];
    __syncthreads();
    if (tid == 0) {
        int r = -1;
        #pragma unroll
        for (int i = 0; i < T; i++)
            if (r < 0 && sm_m[i] >= 0) r = rel_ids[sm_m[i]];
        sm_rel = r;
    }
    __syncthreads();
    const int r_id = sm_rel;
    if (r_id < 0) return;            // dead padding block (uniform exit)

    // ---- setup: u vectors + e in smem; thread c owns column c ----
    {
        const int c = tid;
        evec[c] = relation_emb[(size_t)r_id * D + c];
        #pragma unroll
        for (int i = 0; i < T; i++) {
            const int m = sm_m[i];
            if (m >= 0) {
                const int b = m / n_per_b;
                const float h = mol_emb[(size_t)b * D + c];
                u[i * 5 + 0][c] = h - entity_emb[(size_t)tail_ids[m] * D + c];
                #pragma unroll
                for (int k = 0; k < K_NEG; k++) {
                    const int nt = tail_ids[neg_indices[m * K_NEG + k]];
                    u[i * 5 + 1 + k][c] = h - entity_emb[(size_t)nt * D + c];
                }
            } else {
                #pragma unroll
                for (int q = 0; q < 5; q++) u[i * 5 + q][c] = 0.f;
            }
        }
    }
    __syncthreads();

    // ---- 40 dot products of R row `tid` against u[0..39] ----
    const float4* __restrict__ Rrow =
        reinterpret_cast<const float4*>(relation_matrix + ((size_t)r_id * D + tid) * D);
    const float4* __restrict__ u4 = reinterpret_cast<const float4*>(u);
    // u4[j * (D/4) + c4] == u[j][4*c4 .. 4*c4+3], warp-uniform address (LDS broadcast)

    float acc[NVEC];
    #pragma unroll
    for (int j = 0; j < NVEC; j++) acc[j] = 0.f;

    float4 rv = __ldg(&Rrow[0]);
    for (int c4 = 0; c4 < D / 4; c4++) {
        const float4 rn = (c4 + 1 < D / 4) ? __ldg(&Rrow[c4 + 1])
                                           : make_float4(0.f, 0.f, 0.f, 0.f);
        #pragma unroll
        for (int j = 0; j < NVEC; j++) {
            const float4 v = u4[j * (D / 4) + c4];
            acc[j] = fmaf(rv.x, v.x, acc[j]);
            acc[j] = fmaf(rv.y, v.y, acc[j]);
            acc[j] = fmaf(rv.z, v.z, acc[j]);
            acc[j] = fmaf(rv.w, v.w, acc[j]);
        }
        rv = rn;
    }

    // ---- per-row score contribution (dot + e_row)^2, reduce over 128 rows ----
    const float e = evec[tid];
    const int warp = tid >> 5;
    const int lane = tid & 31;
    #pragma unroll
    for (int j = 0; j < NVEC; j++) {
        float s = acc[j] + e;
        s *= s;
        #pragma unroll
        for (int off = 16; off > 0; off >>= 1)
            s += __shfl_down_sync(0xFFFFFFFFu, s, off);
        if (lane == 0) red[warp][j] = s;
    }
    __syncthreads();

    if (tid < T) {
        const int m = sm_m[tid];
        if (m >= 0) {
            float sc[5];
            #pragma unroll
            for (int q = 0; q < 5; q++)
                sc[q] = red[0][tid * 5 + q] + red[1][tid * 5 + q] +
                        red[2][tid * 5 + q] + red[3][tid * 5 + q];
            const float neg_mean = (sc[1] + sc[2] + sc[3] + sc[4]) * 0.25f;
            const float x = neg_mean - sc[0];
            // sigmoid: large -x -> expf=inf -> sig=0, matches ref's +1e-12 guard
            const float sig = 1.0f / (1.0f + expf(-x));
            g_loss[m] = -logf(sig + 1e-12f);
        }
    }
}

// K5: deterministic single-block tree reduce: out = (sum_m loss_m) / B.
// M is a multiple of 4 (M = B*NEIGH).
__global__ void __launch_bounds__(1024) kg_reduce_kernel(
    float* __restrict__ out, int M, float invB)
{
    __shared__ float s[1024];
    const float4* __restrict__ g4 = reinterpret_cast<const float4*>(g_loss);
    const int n4 = M >> 2;
    float sum = 0.f;
    for (int i = threadIdx.x; i < n4; i += 1024) {
        const float4 v = g4[i];
        sum += (v.x + v.y) + (v.z + v.w);
    }
    s[threadIdx.x] = sum;
    __syncthreads();
    #pragma unroll
    for (int st = 512; st > 0; st >>= 1) {
        if (threadIdx.x < st) s[threadIdx.x] += s[threadIdx.x + st];
        __syncthreads();
    }
    if (threadIdx.x == 0) out[0] = s[0] * invB;
}

extern "C" void kernel_launch(void* const* d_in, const int* in_sizes, int n_in,
                              void* d_out, int out_size)
{
    const float* mol_emb         = (const float*)d_in[0];
    const float* entity_emb      = (const float*)d_in[1];
    const float* relation_emb    = (const float*)d_in[2];
    const float* relation_matrix = (const float*)d_in[3];
    const int*   tail_ids        = (const int*)d_in[4];
    const int*   rel_ids         = (const int*)d_in[5];
    const int*   neg_indices     = (const int*)d_in[6];
    float* out = (float*)d_out;

    const int B = in_sizes[0] / D;                 // 512
    int n_rel = in_sizes[2] / D;                   // 64
    if (n_rel > MAX_REL) n_rel = MAX_REL;
    int M = in_sizes[5];                           // 8192
    if (M > MAX_M) M = MAX_M;
    const int n_per_b = M / B;                     // 16

    const int NB   = M / T + n_rel;                // upper bound on padded tiles
    const int npad = NB * T;

    kg_init_kernel<<<(npad + 255) / 256, 256>>>(npad);
    kg_count_kernel<<<(M + 255) / 256, 256>>>(rel_ids, M);
    kg_offset_kernel<<<1, 32>>>(n_rel);
    kg_scatter_kernel<<<(M + 255) / 256, 256>>>(rel_ids, M);
    kg_score_kernel<<<NB, 128>>>(mol_emb, entity_emb, relation_emb,
                                 relation_matrix, tail_ids, rel_ids,
                                 neg_indices, n_per_b);
    kg_reduce_kernel<<<1, 1024>>>(out, M, 1.0f / (float)B);
}